// round 13
// baseline (speedup 1.0000x reference)
#include <cuda_runtime.h>
#include <cuda_fp16.h>
#include <cstdint>

#define D 128
#define NG 64
#define CO 16
#define MAXN 50176
#define MAXE 600064
#define NEG 0.1f
#define HST 136   // smem row stride in halves

// -------- scratch (device globals: allocation-free workaround) --------
__device__ __half g_ha[MAXN * D];     // GEMM outputs, pre-scaled by dinv[row]
__device__ __half g_hb[MAXN * D];     // gcn layer-1 output
__device__ __half g_WH1[D * D];       // W1^T fp16
__device__ __half g_WH2[D * D];       // W2^T fp16
__device__ float  g_dinv[MAXN];
__device__ int    g_degi[MAXN];
__device__ int    g_rowptr[MAXN + 1];
__device__ int    g_erank[MAXE];
__device__ int    g_csr_src[MAXE];
__device__ int    g_bpub[64];
__device__ float  g_pool[NG * D];
__device__ float  g_cnt[NG];

__device__ __forceinline__ float lrelu(float v) {
    return v >= 0.0f ? v : NEG * v;
}
__device__ __forceinline__ uint32_t hadd2u(uint32_t a, uint32_t b) {
    __half2 r = __hadd2(*(__half2*)&a, *(__half2*)&b);
    return *(uint32_t*)&r;
}
__device__ __forceinline__ void mma16(float* c, const uint32_t* a, uint32_t b0, uint32_t b1) {
    asm volatile(
        "mma.sync.aligned.m16n8k16.row.col.f32.f16.f16.f32 "
        "{%0,%1,%2,%3}, {%4,%5,%6,%7}, {%8,%9}, {%0,%1,%2,%3};"
        : "+f"(c[0]), "+f"(c[1]), "+f"(c[2]), "+f"(c[3])
        : "r"(a[0]), "r"(a[1]), "r"(a[2]), "r"(a[3]), "r"(b0), "r"(b1));
}

// -------- init: zero degi/pool/cnt/bpub + fp16 W^T for both layers --------
__global__ void k_init(const float* __restrict__ W1, const float* __restrict__ W2, int n) {
    int stride = gridDim.x * blockDim.x;
    int i0 = blockIdx.x * blockDim.x + threadIdx.x;
    for (int i = i0; i < n; i += stride) g_degi[i] = 0;
    for (int i = i0; i < NG * D; i += stride) g_pool[i] = 0.0f;
    for (int i = i0; i < NG; i += stride) g_cnt[i] = 0.0f;
    for (int i = i0; i < 64; i += stride) g_bpub[i] = 0;
    for (int i = i0; i < D * D; i += stride) {
        int nn = i >> 7, k = i & 127;
        g_WH1[i] = __float2half_rn(W1[k * D + nn]);
        g_WH2[i] = __float2half_rn(W2[k * D + nn]);
    }
}

// -------- histogram over dst (record per-edge rank) + graph node counts --------
__global__ void k_hist(const int* __restrict__ dst, const int* __restrict__ batch,
                       int E, int n) {
    int stride = gridDim.x * blockDim.x;
    int i0 = blockIdx.x * blockDim.x + threadIdx.x;
    for (int e = i0; e < E; e += stride)
        g_erank[e] = atomicAdd(&g_degi[dst[e]], 1);
    for (int i = i0; i < n; i += stride)
        atomicAdd(&g_cnt[batch[i]], 1.0f);
}

// -------- single-kernel scan: decoupled lookback --------
__global__ void k_scan(int n, int nblk) {
    __shared__ int sm[1024];
    __shared__ int s_off;
    int t = threadIdx.x, b = blockIdx.x;
    int i = b * 1024 + t;
    int d = (i < n) ? g_degi[i] : 0;
    sm[t] = d;
    __syncthreads();
    #pragma unroll
    for (int off = 1; off < 1024; off <<= 1) {
        int u = (t >= off) ? sm[t - off] : 0;
        __syncthreads();
        sm[t] += u;
        __syncthreads();
    }
    if (t == 0) atomicExch(&g_bpub[b], sm[1023] + 1);
    if (t < 32) {
        int acc = 0;
        for (int j = t; j < b; j += 32) {
            int v;
            do { v = atomicAdd(&g_bpub[j], 0); } while (v == 0);
            acc += v - 1;
        }
        #pragma unroll
        for (int off = 16; off; off >>= 1) acc += __shfl_down_sync(~0u, acc, off);
        if (t == 0) s_off = acc;
    }
    __syncthreads();
    int off = s_off;
    if (i < n) {
        g_rowptr[i] = off + sm[t] - d;
        g_dinv[i] = rsqrtf((float)d + 1.0f);
    }
    if (b == nblk - 1 && t == 1023) g_rowptr[n] = off + sm[1023];
}

// -------- permute edges into CSR (atomic-free, rank-based) --------
__global__ void k_permute(const int* __restrict__ src, const int* __restrict__ dst, int E) {
    int stride = gridDim.x * blockDim.x;
    for (int e = blockIdx.x * blockDim.x + threadIdx.x; e < E; e += stride) {
        int d = dst[e];
        g_csr_src[g_rowptr[d] + g_erank[e]] = src[e];
    }
}

// ===================== fp16 HMMA GEMM (m16n8k16, 4m x 2n warp grid) =============
// outh[r,:] = dinv[r] * (A[r,:] @ W)
__global__ void __launch_bounds__(256, 2)
k_gemm(const float* __restrict__ Af, const __half* __restrict__ Ah,
       const __half* __restrict__ Bt, __half* __restrict__ outh, int n) {
    extern __shared__ __half smh[];
    __half* As = smh;
    __half* Bs = smh + 128 * HST;

    int t = threadIdx.x;
    int r0 = blockIdx.x * 128;
    int rows = n - r0;
    if (rows > 128) rows = 128;

    for (int i = t; i < 128 * 32; i += 256) {
        int row = i >> 5, c4 = i & 31;
        *(uint2*)&Bs[row * HST + c4 * 4] = ((const uint2*)Bt)[i];
        uint2 av = make_uint2(0u, 0u);
        if (row < rows) {
            if (Af) {
                float4 v = ((const float4*)(Af + (size_t)r0 * D))[i];
                __half2 h01 = __floats2half2_rn(v.x, v.y);
                __half2 h23 = __floats2half2_rn(v.z, v.w);
                av.x = *(uint32_t*)&h01;
                av.y = *(uint32_t*)&h23;
            } else {
                av = ((const uint2*)(Ah + (size_t)r0 * D))[i];
            }
        }
        *(uint2*)&As[row * HST + c4 * 4] = av;
    }
    __syncthreads();

    int wid = t >> 5, lane = t & 31;
    int gid = lane >> 2, tig = lane & 3;
    int wm = wid >> 1, wn = wid & 1;

    float acc[2][8][4];
    #pragma unroll
    for (int s = 0; s < 2; s++)
        #pragma unroll
        for (int nt = 0; nt < 8; nt++)
            #pragma unroll
            for (int q = 0; q < 4; q++) acc[s][nt][q] = 0.0f;

    int ar0 = (wm * 32 + gid) * HST;
    int ar1 = (wm * 32 + 8 + gid) * HST;
    int ar2 = (wm * 32 + 16 + gid) * HST;
    int ar3 = (wm * 32 + 24 + gid) * HST;

    #pragma unroll
    for (int k16 = 0; k16 < D; k16 += 16) {
        int c0 = k16 + 2 * tig;
        uint32_t a0[4], a1[4];
        a0[0] = *(const uint32_t*)&As[ar0 + c0];
        a0[1] = *(const uint32_t*)&As[ar1 + c0];
        a0[2] = *(const uint32_t*)&As[ar0 + c0 + 8];
        a0[3] = *(const uint32_t*)&As[ar1 + c0 + 8];
        a1[0] = *(const uint32_t*)&As[ar2 + c0];
        a1[1] = *(const uint32_t*)&As[ar3 + c0];
        a1[2] = *(const uint32_t*)&As[ar2 + c0 + 8];
        a1[3] = *(const uint32_t*)&As[ar3 + c0 + 8];

        #pragma unroll
        for (int nt = 0; nt < 8; nt++) {
            int br = (wn * 64 + nt * 8 + gid) * HST + c0;
            uint32_t b0 = *(const uint32_t*)&Bs[br];
            uint32_t b1 = *(const uint32_t*)&Bs[br + 8];
            mma16(acc[0][nt], a0, b0, b1);
            mma16(acc[1][nt], a1, b0, b1);
        }
    }

    #pragma unroll
    for (int s = 0; s < 2; s++) {
        int m0 = wm * 32 + s * 16 + gid;
        int m1 = m0 + 8;
        const int col = wn * 64 + 2 * tig;
        float d0 = (m0 < rows) ? g_dinv[r0 + m0] : 0.f;
        float d1 = (m1 < rows) ? g_dinv[r0 + m1] : 0.f;
        #pragma unroll
        for (int nt = 0; nt < 8; nt++) {
            float* a01 = acc[s][nt];
            if (m0 < rows) {
                __half2 h = __floats2half2_rn(a01[0] * d0, a01[1] * d0);
                *(__half2*)&outh[(size_t)(r0 + m0) * D + col + nt * 8] = h;
            }
            if (m1 < rows) {
                __half2 h = __floats2half2_rn(a01[2] * d1, a01[3] * d1);
                *(__half2*)&outh[(size_t)(r0 + m1) * D + col + nt * 8] = h;
            }
        }
    }
}

// ===================== gather: 2 edges/load, HADD2 accumulate ====================
// lanes 0-15 take even edges, 16-31 odd; lane handles halves [li*8, li*8+8).
// Result (fp32, bias+lrelu applied) valid in lanes 0-15 as r0 (cols li*8..+3),
// r1 (cols li*8+4..+7).
__device__ __forceinline__ void gcn_body(const __half* __restrict__ hh,
                                         const float* __restrict__ bias,
                                         int node, int lane,
                                         float4& r0, float4& r1) {
    int beg = g_rowptr[node], end = g_rowptr[node + 1];
    float di = g_dinv[node];
    int half = lane >> 4, li = lane & 15;
    const uint4* H = (const uint4*)hh;      // row = 16 uint4

    uint32_t aA0 = 0, aA1 = 0, aA2 = 0, aA3 = 0;
    uint32_t aB0 = 0, aB1 = 0, aB2 = 0, aB3 = 0;

    int e = beg;
    for (; e + 4 <= end; e += 4) {
        int s0 = g_csr_src[e + half];
        int s1 = g_csr_src[e + 2 + half];
        uint4 q0 = H[s0 * 16 + li];
        uint4 q1 = H[s1 * 16 + li];
        aA0 = hadd2u(aA0, q0.x); aA1 = hadd2u(aA1, q0.y);
        aA2 = hadd2u(aA2, q0.z); aA3 = hadd2u(aA3, q0.w);
        aB0 = hadd2u(aB0, q1.x); aB1 = hadd2u(aB1, q1.y);
        aB2 = hadd2u(aB2, q1.z); aB3 = hadd2u(aB3, q1.w);
    }
    for (; e < end; e += 2) {
        int idx = e + half;
        bool v = idx < end;
        int s0 = g_csr_src[v ? idx : end - 1];
        uint4 q0 = H[s0 * 16 + li];
        if (v) {
            aA0 = hadd2u(aA0, q0.x); aA1 = hadd2u(aA1, q0.y);
            aA2 = hadd2u(aA2, q0.z); aA3 = hadd2u(aA3, q0.w);
        }
    }
    // merge banks
    aA0 = hadd2u(aA0, aB0); aA1 = hadd2u(aA1, aB1);
    aA2 = hadd2u(aA2, aB2); aA3 = hadd2u(aA3, aB3);
    // merge even/odd half-warps (both halves end with the full sum)
    aA0 = hadd2u(aA0, __shfl_xor_sync(~0u, aA0, 16));
    aA1 = hadd2u(aA1, __shfl_xor_sync(~0u, aA1, 16));
    aA2 = hadd2u(aA2, __shfl_xor_sync(~0u, aA2, 16));
    aA3 = hadd2u(aA3, __shfl_xor_sync(~0u, aA3, 16));
    // self row (h' already scaled by dinv[node])
    uint4 qs = H[node * 16 + li];
    aA0 = hadd2u(aA0, qs.x); aA1 = hadd2u(aA1, qs.y);
    aA2 = hadd2u(aA2, qs.z); aA3 = hadd2u(aA3, qs.w);

    float2 f0 = __half22float2(*(__half2*)&aA0);
    float2 f1 = __half22float2(*(__half2*)&aA1);
    float2 f2 = __half22float2(*(__half2*)&aA2);
    float2 f3 = __half22float2(*(__half2*)&aA3);
    float4 b0 = ((const float4*)bias)[li * 2];
    float4 b1 = ((const float4*)bias)[li * 2 + 1];
    r0.x = lrelu(di * f0.x + b0.x);
    r0.y = lrelu(di * f0.y + b0.y);
    r0.z = lrelu(di * f1.x + b0.z);
    r0.w = lrelu(di * f1.y + b0.w);
    r1.x = lrelu(di * f2.x + b1.x);
    r1.y = lrelu(di * f2.y + b1.y);
    r1.z = lrelu(di * f3.x + b1.z);
    r1.w = lrelu(di * f3.y + b1.w);
}

__global__ void k_gcn(const __half* __restrict__ hh, const float* __restrict__ bias,
                      __half* __restrict__ outh, int n) {
    int node = blockIdx.x * 8 + (threadIdx.x >> 5);
    if (node >= n) return;
    int lane = threadIdx.x & 31;
    float4 r0, r1;
    gcn_body(hh, bias, node, lane, r0, r1);
    if (lane < 16) {
        __half2 h0 = __floats2half2_rn(r0.x, r0.y);
        __half2 h1 = __floats2half2_rn(r0.z, r0.w);
        __half2 h2 = __floats2half2_rn(r1.x, r1.y);
        __half2 h3 = __floats2half2_rn(r1.z, r1.w);
        uint4 o;
        o.x = *(uint32_t*)&h0; o.y = *(uint32_t*)&h1;
        o.z = *(uint32_t*)&h2; o.w = *(uint32_t*)&h3;
        ((uint4*)(outh + (size_t)node * D))[lane] = o;
    }
}

__global__ void k_gcn_pool(const __half* __restrict__ hh, const float* __restrict__ bias,
                           const int* __restrict__ batch, int n) {
    int node = blockIdx.x * 8 + (threadIdx.x >> 5);
    if (node >= n) return;
    int lane = threadIdx.x & 31;
    float4 r0, r1;
    gcn_body(hh, bias, node, lane, r0, r1);
    if (lane < 16) {
        int gid = batch[node];
        float4* p = ((float4*)g_pool) + gid * 32 + lane * 2;
        atomicAdd(p, r0);
        atomicAdd(p + 1, r1);
    }
}

// -------- head: out[g,c] = (pool[g]/cnt[g]) @ Wl + bl --------
__global__ void k_final(const float* __restrict__ Wl, const float* __restrict__ bl,
                        float* __restrict__ out) {
    int t = threadIdx.x;
    int g = t >> 4;
    int c = t & 15;
    float cnt = fmaxf(g_cnt[g], 1.0f);
    float s = 0.0f;
    #pragma unroll 8
    for (int f = 0; f < D; f++)
        s += g_pool[g * D + f] * Wl[f * CO + c];
    out[g * CO + c] = s / cnt + bl[c];
}

extern "C" void kernel_launch(void* const* d_in, const int* in_sizes, int n_in,
                              void* d_out, int out_size) {
    const float* x     = (const float*)d_in[0];
    const int*   ei    = (const int*)d_in[1];
    const int*   batch = (const int*)d_in[2];
    const float* W1    = (const float*)d_in[3];
    const float* b1    = (const float*)d_in[4];
    const float* W2    = (const float*)d_in[5];
    const float* b2    = (const float*)d_in[6];
    const float* Wl    = (const float*)d_in[7];
    const float* bl    = (const float*)d_in[8];

    int n = in_sizes[0] / D;
    int E = in_sizes[1] / 2;
    const int* src = ei;
    const int* dst = ei + E;

    void *pha, *phb, *pwh1, *pwh2;
    cudaGetSymbolAddress(&pha, g_ha);
    cudaGetSymbolAddress(&phb, g_hb);
    cudaGetSymbolAddress(&pwh1, g_WH1);
    cudaGetSymbolAddress(&pwh2, g_WH2);
    __half* ha = (__half*)pha;
    __half* hb = (__half*)phb;

    int smem = 2 * 128 * HST * (int)sizeof(__half);   // 69632 B
    cudaFuncSetAttribute(k_gemm, cudaFuncAttributeMaxDynamicSharedMemorySize, smem);

    int nblk = (n + 1023) / 1024;
    int nblocks8 = (n + 7) / 8;
    int gtiles = (n + 127) / 128;

    // CSR build
    k_init<<<512, 256>>>(W1, W2, n);
    k_hist<<<1024, 256>>>(dst, batch, E, n);
    k_scan<<<nblk, 1024>>>(n, nblk);
    k_permute<<<1024, 256>>>(src, dst, E);

    // Layer 1: ha = dinv*(x@W1) ; hb = gcn(ha)
    k_gemm<<<gtiles, 256, smem>>>(x, nullptr, (__half*)pwh1, ha, n);
    k_gcn<<<nblocks8, 256>>>(ha, b1, hb, n);

    // Layer 2: ha = dinv*(hb@W2) ; pool += gcn(ha)
    k_gemm<<<gtiles, 256, smem>>>(nullptr, hb, (__half*)pwh2, ha, n);
    k_gcn_pool<<<nblocks8, 256>>>(ha, b2, batch, n);

    // Head
    k_final<<<1, 1024>>>(Wl, bl, (float*)d_out);
}

// round 14
// speedup vs baseline: 1.2365x; 1.2365x over previous
#include <cuda_runtime.h>
#include <cuda_fp16.h>
#include <cstdint>

#define D 128
#define NG 64
#define CO 16
#define MAXN 50176
#define MAXE 600064
#define NEG 0.1f
#define HST 136   // smem row stride in halves

// -------- scratch (device globals: zero-initialized at load; self-cleaning) -----
__device__ __half g_ha[MAXN * D];     // GEMM outputs, pre-scaled by dinv[row]
__device__ __half g_hb[MAXN * D];     // gcn layer-1 output
__device__ __half g_WH1[D * D];       // W1^T fp16
__device__ __half g_WH2[D * D];       // W2^T fp16
__device__ float  g_dinv[MAXN];
__device__ int    g_degi[MAXN];       // zeroed by k_scan after use
__device__ int    g_rowptr[MAXN + 1];
__device__ int    g_erank[MAXE];
__device__ int    g_csr_src[MAXE];
__device__ int    g_bpub[64];         // zeroed by k_permute after use
__device__ float  g_pool[NG * D];     // zeroed by k_final after use
__device__ float  g_cnt[NG];          // zeroed by k_final after use

__device__ __forceinline__ float lrelu(float v) {
    return v >= 0.0f ? v : NEG * v;
}
__device__ __forceinline__ void mma16(float* c, const uint32_t* a, uint32_t b0, uint32_t b1) {
    asm volatile(
        "mma.sync.aligned.m16n8k16.row.col.f32.f16.f16.f32 "
        "{%0,%1,%2,%3}, {%4,%5,%6,%7}, {%8,%9}, {%0,%1,%2,%3};"
        : "+f"(c[0]), "+f"(c[1]), "+f"(c[2]), "+f"(c[3])
        : "r"(a[0]), "r"(a[1]), "r"(a[2]), "r"(a[3]), "r"(b0), "r"(b1));
}

// -------- hist: degree over dst (+ per-edge rank), graph counts, W fp16 splits ---
__global__ void k_hist(const int* __restrict__ dst, const int* __restrict__ batch,
                       const float* __restrict__ W1, const float* __restrict__ W2,
                       int E, int n) {
    int stride = gridDim.x * blockDim.x;
    int i0 = blockIdx.x * blockDim.x + threadIdx.x;
    for (int e = i0; e < E; e += stride)
        g_erank[e] = atomicAdd(&g_degi[dst[e]], 1);
    for (int i = i0; i < n; i += stride)
        atomicAdd(&g_cnt[batch[i]], 1.0f);
    for (int i = i0; i < D * D; i += stride) {
        int nn = i >> 7, k = i & 127;
        g_WH1[i] = __float2half_rn(W1[k * D + nn]);
        g_WH2[i] = __float2half_rn(W2[k * D + nn]);
    }
}

// -------- single-kernel scan: decoupled lookback; re-zeroes degi --------
__global__ void k_scan(int n, int nblk) {
    __shared__ int sm[1024];
    __shared__ int s_off;
    int t = threadIdx.x, b = blockIdx.x;
    int i = b * 1024 + t;
    int d = (i < n) ? g_degi[i] : 0;
    sm[t] = d;
    __syncthreads();
    #pragma unroll
    for (int off = 1; off < 1024; off <<= 1) {
        int u = (t >= off) ? sm[t - off] : 0;
        __syncthreads();
        sm[t] += u;
        __syncthreads();
    }
    if (t == 0) atomicExch(&g_bpub[b], sm[1023] + 1);
    if (t < 32) {
        int acc = 0;
        for (int j = t; j < b; j += 32) {
            int v;
            do { v = atomicAdd(&g_bpub[j], 0); } while (v == 0);
            acc += v - 1;
        }
        #pragma unroll
        for (int off = 16; off; off >>= 1) acc += __shfl_down_sync(~0u, acc, off);
        if (t == 0) s_off = acc;
    }
    __syncthreads();
    int off = s_off;
    if (i < n) {
        g_rowptr[i] = off + sm[t] - d;
        g_dinv[i] = rsqrtf((float)d + 1.0f);
        g_degi[i] = 0;                      // restore for next replay
    }
    if (b == nblk - 1 && t == 1023) g_rowptr[n] = off + sm[1023];
}

// -------- permute edges into CSR (atomic-free); re-zeroes bpub --------
__global__ void k_permute(const int* __restrict__ src, const int* __restrict__ dst, int E) {
    int stride = gridDim.x * blockDim.x;
    for (int e = blockIdx.x * blockDim.x + threadIdx.x; e < E; e += stride) {
        int d = dst[e];
        g_csr_src[g_rowptr[d] + g_erank[e]] = src[e];
    }
    if (blockIdx.x == 0 && threadIdx.x < 64) g_bpub[threadIdx.x] = 0;
}

// ===================== fp16 HMMA GEMM (m16n8k16, 4m x 2n warp grid) =============
// outh[r,:] = dinv[r] * (A[r,:] @ W)
__global__ void __launch_bounds__(256, 2)
k_gemm(const float* __restrict__ Af, const __half* __restrict__ Ah,
       const __half* __restrict__ Bt, __half* __restrict__ outh, int n) {
    extern __shared__ __half smh[];
    __half* As = smh;
    __half* Bs = smh + 128 * HST;

    int t = threadIdx.x;
    int r0 = blockIdx.x * 128;
    int rows = n - r0;
    if (rows > 128) rows = 128;

    for (int i = t; i < 128 * 32; i += 256) {
        int row = i >> 5, c4 = i & 31;
        *(uint2*)&Bs[row * HST + c4 * 4] = ((const uint2*)Bt)[i];
        uint2 av = make_uint2(0u, 0u);
        if (row < rows) {
            if (Af) {
                float4 v = ((const float4*)(Af + (size_t)r0 * D))[i];
                __half2 h01 = __floats2half2_rn(v.x, v.y);
                __half2 h23 = __floats2half2_rn(v.z, v.w);
                av.x = *(uint32_t*)&h01;
                av.y = *(uint32_t*)&h23;
            } else {
                av = ((const uint2*)(Ah + (size_t)r0 * D))[i];
            }
        }
        *(uint2*)&As[row * HST + c4 * 4] = av;
    }
    __syncthreads();

    int wid = t >> 5, lane = t & 31;
    int gid = lane >> 2, tig = lane & 3;
    int wm = wid >> 1, wn = wid & 1;

    float acc[2][8][4];
    #pragma unroll
    for (int s = 0; s < 2; s++)
        #pragma unroll
        for (int nt = 0; nt < 8; nt++)
            #pragma unroll
            for (int q = 0; q < 4; q++) acc[s][nt][q] = 0.0f;

    int ar0 = (wm * 32 + gid) * HST;
    int ar1 = (wm * 32 + 8 + gid) * HST;
    int ar2 = (wm * 32 + 16 + gid) * HST;
    int ar3 = (wm * 32 + 24 + gid) * HST;

    #pragma unroll
    for (int k16 = 0; k16 < D; k16 += 16) {
        int c0 = k16 + 2 * tig;
        uint32_t a0[4], a1[4];
        a0[0] = *(const uint32_t*)&As[ar0 + c0];
        a0[1] = *(const uint32_t*)&As[ar1 + c0];
        a0[2] = *(const uint32_t*)&As[ar0 + c0 + 8];
        a0[3] = *(const uint32_t*)&As[ar1 + c0 + 8];
        a1[0] = *(const uint32_t*)&As[ar2 + c0];
        a1[1] = *(const uint32_t*)&As[ar3 + c0];
        a1[2] = *(const uint32_t*)&As[ar2 + c0 + 8];
        a1[3] = *(const uint32_t*)&As[ar3 + c0 + 8];

        #pragma unroll
        for (int nt = 0; nt < 8; nt++) {
            int br = (wn * 64 + nt * 8 + gid) * HST + c0;
            uint32_t b0 = *(const uint32_t*)&Bs[br];
            uint32_t b1 = *(const uint32_t*)&Bs[br + 8];
            mma16(acc[0][nt], a0, b0, b1);
            mma16(acc[1][nt], a1, b0, b1);
        }
    }

    #pragma unroll
    for (int s = 0; s < 2; s++) {
        int m0 = wm * 32 + s * 16 + gid;
        int m1 = m0 + 8;
        const int col = wn * 64 + 2 * tig;
        float d0 = (m0 < rows) ? g_dinv[r0 + m0] : 0.f;
        float d1 = (m1 < rows) ? g_dinv[r0 + m1] : 0.f;
        #pragma unroll
        for (int nt = 0; nt < 8; nt++) {
            float* a01 = acc[s][nt];
            if (m0 < rows) {
                __half2 h = __floats2half2_rn(a01[0] * d0, a01[1] * d0);
                *(__half2*)&outh[(size_t)(r0 + m0) * D + col + nt * 8] = h;
            }
            if (m1 < rows) {
                __half2 h = __floats2half2_rn(a01[2] * d1, a01[3] * d1);
                *(__half2*)&outh[(size_t)(r0 + m1) * D + col + nt * 8] = h;
            }
        }
    }
}

// ===================== gather (R12 shape: dinv-folded row sum) ====================
__device__ __forceinline__ void add_row(float4& acc, uint2 q) {
    float2 a0 = __half22float2(*(__half2*)&q.x);
    float2 a1 = __half22float2(*(__half2*)&q.y);
    acc.x += a0.x; acc.y += a0.y;
    acc.z += a1.x; acc.w += a1.y;
}

__device__ __forceinline__ void gcn_body(const __half* __restrict__ hh,
                                         const float* __restrict__ bias,
                                         int node, int lane, float4& r) {
    int beg = g_rowptr[node], end = g_rowptr[node + 1];
    float di = g_dinv[node];

    float4 acc = make_float4(0.f, 0.f, 0.f, 0.f);
    add_row(acc, ((const uint2*)(hh + (size_t)node * D))[lane]);

    int e = beg;
    for (; e + 4 <= end; e += 4) {
        int s0 = g_csr_src[e];
        int s1 = g_csr_src[e + 1];
        int s2 = g_csr_src[e + 2];
        int s3 = g_csr_src[e + 3];
        uint2 q0 = ((const uint2*)(hh + (size_t)s0 * D))[lane];
        uint2 q1 = ((const uint2*)(hh + (size_t)s1 * D))[lane];
        uint2 q2 = ((const uint2*)(hh + (size_t)s2 * D))[lane];
        uint2 q3 = ((const uint2*)(hh + (size_t)s3 * D))[lane];
        add_row(acc, q0); add_row(acc, q1);
        add_row(acc, q2); add_row(acc, q3);
    }
    for (; e < end; e++) {
        int s0 = g_csr_src[e];
        add_row(acc, ((const uint2*)(hh + (size_t)s0 * D))[lane]);
    }

    float4 b = ((const float4*)bias)[lane];
    r.x = lrelu(di * acc.x + b.x);
    r.y = lrelu(di * acc.y + b.y);
    r.z = lrelu(di * acc.z + b.z);
    r.w = lrelu(di * acc.w + b.w);
}

__global__ void k_gcn(const __half* __restrict__ hh, const float* __restrict__ bias,
                      __half* __restrict__ outh, int n) {
    int node = blockIdx.x * 8 + (threadIdx.x >> 5);
    if (node >= n) return;
    int lane = threadIdx.x & 31;
    float4 r;
    gcn_body(hh, bias, node, lane, r);
    __half2 o01 = __floats2half2_rn(r.x, r.y);
    __half2 o23 = __floats2half2_rn(r.z, r.w);
    uint2 o;
    o.x = *(uint32_t*)&o01;
    o.y = *(uint32_t*)&o23;
    ((uint2*)(outh + (size_t)node * D))[lane] = o;
}

__global__ void k_gcn_pool(const __half* __restrict__ hh, const float* __restrict__ bias,
                           const int* __restrict__ batch, int n) {
    int node = blockIdx.x * 8 + (threadIdx.x >> 5);
    if (node >= n) return;
    int lane = threadIdx.x & 31;
    float4 r;
    gcn_body(hh, bias, node, lane, r);
    int gid = batch[node];
    atomicAdd(((float4*)g_pool) + gid * 32 + lane, r);
}

// -------- head: out = (pool/cnt) @ Wl + bl; re-zeroes pool/cnt --------
__global__ void k_final(const float* __restrict__ Wl, const float* __restrict__ bl,
                        float* __restrict__ out) {
    int t = threadIdx.x;
    int g = t >> 4;
    int c = t & 15;
    float cnt = fmaxf(g_cnt[g], 1.0f);
    float s = 0.0f;
    #pragma unroll 8
    for (int f = 0; f < D; f++)
        s += g_pool[g * D + f] * Wl[f * CO + c];
    out[g * CO + c] = s / cnt + bl[c];
    __syncthreads();
    // restore scratch for next replay
    #pragma unroll
    for (int i = 0; i < NG * D / 1024; i++)
        g_pool[t + i * 1024] = 0.0f;
    if (t < NG) g_cnt[t] = 0.0f;
}

extern "C" void kernel_launch(void* const* d_in, const int* in_sizes, int n_in,
                              void* d_out, int out_size) {
    const float* x     = (const float*)d_in[0];
    const int*   ei    = (const int*)d_in[1];
    const int*   batch = (const int*)d_in[2];
    const float* W1    = (const float*)d_in[3];
    const float* b1    = (const float*)d_in[4];
    const float* W2    = (const float*)d_in[5];
    const float* b2    = (const float*)d_in[6];
    const float* Wl    = (const float*)d_in[7];
    const float* bl    = (const float*)d_in[8];

    int n = in_sizes[0] / D;
    int E = in_sizes[1] / 2;
    const int* src = ei;
    const int* dst = ei + E;

    void *pha, *phb, *pwh1, *pwh2;
    cudaGetSymbolAddress(&pha, g_ha);
    cudaGetSymbolAddress(&phb, g_hb);
    cudaGetSymbolAddress(&pwh1, g_WH1);
    cudaGetSymbolAddress(&pwh2, g_WH2);
    __half* ha = (__half*)pha;
    __half* hb = (__half*)phb;

    int smem = 2 * 128 * HST * (int)sizeof(__half);   // 69632 B
    cudaFuncSetAttribute(k_gemm, cudaFuncAttributeMaxDynamicSharedMemorySize, smem);

    int nblk = (n + 1023) / 1024;
    int nblocks8 = (n + 7) / 8;
    int gtiles = (n + 127) / 128;

    // CSR build (3 launches, self-cleaning)
    k_hist<<<1024, 256>>>(dst, batch, W1, W2, E, n);
    k_scan<<<nblk, 1024>>>(n, nblk);
    k_permute<<<1024, 256>>>(src, dst, E);

    // Layer 1: ha = dinv*(x@W1) ; hb = gcn(ha)
    k_gemm<<<gtiles, 256, smem>>>(x, nullptr, (__half*)pwh1, ha, n);
    k_gcn<<<nblocks8, 256>>>(ha, b1, hb, n);

    // Layer 2: ha = dinv*(hb@W2) ; pool += gcn(ha)
    k_gemm<<<gtiles, 256, smem>>>(nullptr, hb, (__half*)pwh2, ha, n);
    k_gcn_pool<<<nblocks8, 256>>>(ha, b2, batch, n);

    // Head
    k_final<<<1, 1024>>>(Wl, bl, (float*)d_out);
}